// round 12
// baseline (speedup 1.0000x reference)
#include <cuda_runtime.h>
#include <algorithm>

static constexpr int NB = 8;
static constexpr int HD = 192;
#define BN_EPS 1e-5f

typedef unsigned long long u64;

// ---------------- scratch (static device memory; no allocations) ----------------
// Activation buffers are NHWC: [b][y][x][c]
__device__ float g_A[(size_t)NB * HD * 256 * 256];
__device__ float g_Bu[(size_t)NB * HD * 128 * 128];
__device__ float g_Cu[(size_t)NB * HD * 128 * 128];
__device__ float g_m0[NB * 256 * 256];
__device__ float g_m1[NB * 128 * 128];
__device__ float g_m2[NB * 64 * 64];
__device__ float g_m3[NB * 32 * 32];
__device__ float g_m4[NB * 16 * 16];
__device__ float g_wt[16 * 192 * 9 * 192];           // [conv][ic][tap][oc]
__device__ float g_stats[2 * HD];
__device__ float g_cnt[5];
__device__ float g_mom[9];                           // masked image moments (stem BN)
__device__ float g_bn2[18 * 2 * HD];

__device__ __forceinline__ float* bufsel(int i) {
    return (i == 0) ? g_A : (i == 1) ? g_Bu : g_Cu;
}
__device__ __forceinline__ float* maskptr(int lvl) {
    switch (lvl) {
        case 0: return g_m0;
        case 1: return g_m1;
        case 2: return g_m2;
        case 3: return g_m3;
        default: return g_m4;
    }
}

// ---------------- packed fp32x2 helpers ----------------
__device__ __forceinline__ void fma2(u64& d, u64 a, u64 b) {
    asm("fma.rn.f32x2 %0, %1, %2, %0;" : "+l"(d) : "l"(a), "l"(b));
}
__device__ __forceinline__ u64 mul2(u64 a, u64 b) {
    u64 d; asm("mul.rn.f32x2 %0, %1, %2;" : "=l"(d) : "l"(a), "l"(b)); return d;
}
__device__ __forceinline__ u64 dup2(float x) {
    unsigned int u = __float_as_uint(x);
    return (u64)u | ((u64)u << 32);
}
__device__ __forceinline__ u64 pack2(float x, float y) {
    u64 d; asm("mov.b64 %0, {%1, %2};" : "=l"(d) : "f"(x), "f"(y)); return d;
}
__device__ __forceinline__ float2 up2(u64 v) {
    float2 f;
    f.x = __uint_as_float((unsigned int)v);
    f.y = __uint_as_float((unsigned int)(v >> 32));
    return f;
}
__device__ __forceinline__ u64 wsel(const ulonglong2* W, int j) {
    return (j & 1) ? W[j >> 1].y : W[j >> 1].x;
}

// ---------------- small utility kernels ----------------
__global__ void k_zcnt() {
    if (threadIdx.x < 5) g_cnt[threadIdx.x] = 0.f;
    if (threadIdx.x < 9) g_mom[threadIdx.x] = 0.f;
}
__global__ void k_zstat() { if (threadIdx.x < 2 * HD) g_stats[threadIdx.x] = 0.f; }

__global__ void k_mask0(const int* __restrict__ mask) {
    int i = blockIdx.x * 256 + threadIdx.x;
    int b = i >> 16, p = i & 65535;
    int y = p >> 8, x = p & 255;
    float v = 1.f - (float)mask[b * 256 + (y >> 4) * 16 + (x >> 4)];
    g_m0[i] = v;
    float s = v;
    for (int o = 16; o; o >>= 1) s += __shfl_down_sync(0xffffffffu, s, o);
    if ((threadIdx.x & 31) == 0) atomicAdd(&g_cnt[0], s);
}

__global__ void k_down(int lvl, int Hin, int Hout) {
    const float* mi = maskptr(lvl - 1);
    float* mo = maskptr(lvl);
    int HW = Hout * Hout;
    int i = blockIdx.x * 256 + threadIdx.x;
    int b = i / HW, p = i - b * HW;
    int y = p / Hout, x = p - y * Hout;
    float mx = 0.f;
    #pragma unroll
    for (int dy = 0; dy < 3; dy++) {
        int yy = 2 * y - 1 + dy;
        if (yy < 0 || yy >= Hin) continue;
        #pragma unroll
        for (int dx = 0; dx < 3; dx++) {
            int xx = 2 * x - 1 + dx;
            if (xx < 0 || xx >= Hin) continue;
            mx = fmaxf(mx, mi[(b * Hin + yy) * Hin + xx]);
        }
    }
    mo[i] = mx;
    float s = mx;
    for (int o = 16; o; o >>= 1) s += __shfl_down_sync(0xffffffffu, s, o);
    if ((threadIdx.x & 31) == 0) atomicAdd(&g_cnt[lvl], s);
}

__global__ void k_wt(const float* __restrict__ dw1, const float* __restrict__ dw2,
                     const float* __restrict__ rw1, const float* __restrict__ rw2) {
    const size_t per = 192 * 9 * 192;
    const size_t total = 16 * per;
    for (size_t i = (size_t)blockIdx.x * blockDim.x + threadIdx.x; i < total;
         i += (size_t)gridDim.x * blockDim.x) {
        int conv = (int)(i / per);
        int r = (int)(i - (size_t)conv * per);
        int ic = r / (9 * 192);
        int r2 = r - ic * (9 * 192);
        int tap = r2 / 192, oc = r2 - tap * 192;
        int layer = conv >> 2, kind = conv & 3;
        const float* src = (kind == 0 ? dw1 : kind == 1 ? dw2 : kind == 2 ? rw1 : rw2)
                           + (size_t)layer * per;
        g_wt[i] = src[(size_t)oc * 1728 + ic * 9 + tap];
    }
}

// stem: 1x1 conv 3->192, NHWC raw output (stats handled analytically)
__global__ void k_stem(const float* __restrict__ img, const float* __restrict__ w) {
    size_t i = (size_t)blockIdx.x * 256 + threadIdx.x;  // NB*65536*96
    int op = (int)(i % 96);
    size_t r = i / 96;
    int p = (int)(r & 65535);
    int b = (int)(r >> 16);
    const float* ib = img + (size_t)b * 196608 + p;
    float i0 = ib[0], i1 = ib[65536], i2 = ib[131072];
    int oc = op * 2;
    float v0 = w[oc * 3 + 0] * i0 + w[oc * 3 + 1] * i1 + w[oc * 3 + 2] * i2;
    float v1 = w[oc * 3 + 3] * i0 + w[oc * 3 + 4] * i1 + w[oc * 3 + 5] * i2;
    *(u64*)&g_A[((size_t)b * 65536 + p) * 192 + oc] = pack2(v0, v1);
}

// masked image moments: M1[3] + M2[6]
__global__ void k_mom(const float* __restrict__ img) {
    float a[9];
    #pragma unroll
    for (int j = 0; j < 9; j++) a[j] = 0.f;
    int N = NB * 65536;
    for (int i = blockIdx.x * 256 + threadIdx.x; i < N; i += gridDim.x * 256) {
        int b = i >> 16, p = i & 65535;
        const float* ib = img + (size_t)b * 196608 + p;
        float m = g_m0[i];
        float c0 = ib[0], c1 = ib[65536], c2 = ib[131072];
        a[0] += c0 * m; a[1] += c1 * m; a[2] += c2 * m;
        a[3] += c0 * c0 * m; a[4] += c0 * c1 * m; a[5] += c0 * c2 * m;
        a[6] += c1 * c1 * m; a[7] += c1 * c2 * m; a[8] += c2 * c2 * m;
    }
    #pragma unroll
    for (int j = 0; j < 9; j++)
        for (int o = 16; o; o >>= 1) a[j] += __shfl_down_sync(0xffffffffu, a[j], o);
    __shared__ float sh[8][9];
    int w = threadIdx.x >> 5, ln = threadIdx.x & 31;
    if (ln == 0) {
        #pragma unroll
        for (int j = 0; j < 9; j++) sh[w][j] = a[j];
    }
    __syncthreads();
    if (threadIdx.x < 9) {
        float s = 0.f;
        #pragma unroll
        for (int k = 0; k < 8; k++) s += sh[k][threadIdx.x];
        atomicAdd(&g_mom[threadIdx.x], s);
    }
}

// stem BN finalize from moments -> slot 0
__global__ void k_finstem(const float* __restrict__ w, const float* __restrict__ g,
                          const float* __restrict__ bt) {
    int c = threadIdx.x;
    float w0 = w[c * 3], w1 = w[c * 3 + 1], w2 = w[c * 3 + 2];
    float cnt = fmaxf(g_cnt[0], 1.f);
    float s = w0 * g_mom[0] + w1 * g_mom[1] + w2 * g_mom[2];
    float ss = w0 * w0 * g_mom[3] + w1 * w1 * g_mom[6] + w2 * w2 * g_mom[8]
             + 2.f * (w0 * w1 * g_mom[4] + w0 * w2 * g_mom[5] + w1 * w2 * g_mom[7]);
    float mean = s / cnt;
    float var = fmaxf(ss / cnt - mean * mean, 0.f);
    float inv = rsqrtf(var + BN_EPS);
    float sc = g[c] * inv;
    g_bn2[c] = sc;
    g_bn2[HD + c] = bt[c] - mean * sc;
}

// fused input transform during staging (NHWC read)
__device__ __forceinline__ float stage_val(const float* __restrict__ inb, int Hin,
                                           int yy, int xx, int c,
                                           const float* __restrict__ bnin,
                                           const float* __restrict__ mski, int inrelu) {
    if ((unsigned)yy >= (unsigned)Hin || (unsigned)xx >= (unsigned)Hin) return 0.f;
    float v = inb[((size_t)yy * Hin + xx) * 192 + c];
    if (bnin) {
        v = (v * bnin[c] + bnin[192 + c]) * mski[yy * Hin + xx];
        if (inrelu) v = fmaxf(v, 0.f);
    }
    return v;
}

// cross-warp stats combine: shared atomics then 128 global REDG
__device__ __forceinline__ void stats_combine(float* s_red, int t, int ln, int ocb,
                                              float2 sv, float2 qv) {
    __syncthreads();
    if (t < 128) s_red[t] = 0.f;
    __syncthreads();
    atomicAdd(&s_red[2 * ln], sv.x);
    atomicAdd(&s_red[2 * ln + 1], sv.y);
    atomicAdd(&s_red[64 + 2 * ln], qv.x);
    atomicAdd(&s_red[64 + 2 * ln + 1], qv.y);
    __syncthreads();
    if (t < 64) {
        atomicAdd(&g_stats[ocb + t], s_red[t]);
        atomicAdd(&g_stats[HD + ocb + t], s_red[64 + t]);
    }
}

// =============== 3x3 conv stride 1, 16x16 tile, 64 oc/block ===============
// 256 threads = 8 warps(2 rows each) x 32 lanes(oc-pair each)
__global__ void __launch_bounds__(256, 2)
k_conv_s1(int srcb, int dstb, int wslot, int H, int inslot, int inrelu, int lvl) {
    constexpr int ICB = 8;
    __shared__ __align__(16) u64 s_in[ICB * 18 * 18];
    __shared__ __align__(16) float s_w[ICB * 9 * 64];
    __shared__ float s_red[128];

    const float* in = bufsel(srcb);
    float* out = bufsel(dstb);
    int tiles = H >> 4;
    int tx0 = (blockIdx.x % tiles) << 4;
    int ty0 = (blockIdx.x / tiles) << 4;
    int b = blockIdx.y;
    int ocb = blockIdx.z * 64;
    int t = threadIdx.x, wrp = t >> 5, ln = t & 31;

    const float* inb = in + (size_t)b * H * H * 192;
    const float* mski = (inslot >= 0) ? maskptr(lvl) + (size_t)b * H * H : nullptr;
    const float* bnin = (inslot >= 0) ? g_bn2 + inslot * 384 : nullptr;
    const int wbase = wslot * 192;

    u64 acc0[16], acc1[16];
    #pragma unroll
    for (int c = 0; c < 16; c++) { acc0[c] = 0ull; acc1[c] = 0ull; }

    for (int ic0 = 0; ic0 < 192; ic0 += ICB) {
        __syncthreads();
        for (int i = t; i < ICB * 9 * 64; i += 256) {
            int icl = i / 576, r = i - icl * 576;
            int tap = r >> 6, j = r & 63;
            s_w[i] = g_wt[((size_t)(wbase + ic0 + icl) * 9 + tap) * 192 + ocb + j];
        }
        for (int i = t; i < ICB * 324; i += 256) {
            int icl = i & 7, pxi = i >> 3;
            int rr = pxi / 18, cc = pxi - rr * 18;
            float v = stage_val(inb, H, ty0 - 1 + rr, tx0 - 1 + cc, ic0 + icl,
                                bnin, mski, inrelu);
            s_in[icl * 324 + rr * 18 + cc] = dup2(v);
        }
        __syncthreads();
        #pragma unroll
        for (int icl = 0; icl < ICB; icl++) {
            const u64* base = s_in + icl * 324;
            const float* wp0 = s_w + icl * 576;
            #pragma unroll
            for (int dy = 0; dy < 3; dy++) {
                u64 w2[3];
                #pragma unroll
                for (int dx = 0; dx < 3; dx++)
                    w2[dx] = reinterpret_cast<const u64*>(wp0 + (dy * 3 + dx) * 64)[ln];
                const u64* rA = base + (2 * wrp + dy) * 18;
                const u64* rB = rA + 18;
                #pragma unroll
                for (int ch = 0; ch < 2; ch++) {
                    ulonglong2 WA[5], WB[5];
                    const ulonglong2* pA = reinterpret_cast<const ulonglong2*>(rA + ch * 8);
                    const ulonglong2* pB = reinterpret_cast<const ulonglong2*>(rB + ch * 8);
                    #pragma unroll
                    for (int k = 0; k < 5; k++) { WA[k] = pA[k]; WB[k] = pB[k]; }
                    #pragma unroll
                    for (int dx = 0; dx < 3; dx++)
                        #pragma unroll
                        for (int c = 0; c < 8; c++) {
                            fma2(acc0[ch * 8 + c], w2[dx], wsel(WA, c + dx));
                            fma2(acc1[ch * 8 + c], w2[dx], wsel(WB, c + dx));
                        }
                }
            }
        }
    }

    const float* mo = maskptr(lvl) + (size_t)b * H * H;
    int oy0 = ty0 + 2 * wrp;
    u64 sum = 0ull, sq = 0ull;
    #pragma unroll
    for (int c = 0; c < 16; c++) {
        u64 m0 = dup2(mo[oy0 * H + tx0 + c]);
        u64 m1 = dup2(mo[(oy0 + 1) * H + tx0 + c]);
        fma2(sum, acc0[c], m0); fma2(sq, mul2(acc0[c], acc0[c]), m0);
        fma2(sum, acc1[c], m1); fma2(sq, mul2(acc1[c], acc1[c]), m1);
    }
    int oc = ocb + 2 * ln;
    float* ob = out + (size_t)b * H * H * 192 + oc;
    #pragma unroll
    for (int c = 0; c < 16; c++) {
        *(u64*)(ob + (size_t)(oy0 * H + tx0 + c) * 192) = acc0[c];
        *(u64*)(ob + (size_t)((oy0 + 1) * H + tx0 + c) * 192) = acc1[c];
    }
    stats_combine(s_red, t, ln, ocb, up2(sum), up2(sq));
}

// =============== 3x3 conv stride 2, 16x16 output tile, 64 oc/block ===============
__global__ void __launch_bounds__(256, 2)
k_conv_s2(int srcb, int dstb, int wslot, int Hout, int inslot, int inrelu, int lvl) {
    constexpr int ICB = 4;
    __shared__ __align__(16) u64 s_in[ICB * 33 * 34];
    __shared__ __align__(16) float s_w[ICB * 9 * 64];
    __shared__ float s_red[128];

    const int Hin = Hout * 2;
    const float* in = bufsel(srcb);
    float* out = bufsel(dstb);
    int tiles = Hout >> 4;
    int tx0 = (blockIdx.x % tiles) << 4;
    int ty0 = (blockIdx.x / tiles) << 4;
    int b = blockIdx.y;
    int ocb = blockIdx.z * 64;
    int t = threadIdx.x, wrp = t >> 5, ln = t & 31;

    const float* inb = in + (size_t)b * Hin * Hin * 192;
    const float* mski = (inslot >= 0) ? maskptr(lvl - 1) + (size_t)b * Hin * Hin : nullptr;
    const float* bnin = (inslot >= 0) ? g_bn2 + inslot * 384 : nullptr;
    const int wbase = wslot * 192;
    int iy0 = ty0 * 2 - 1, ix0 = tx0 * 2 - 1;

    u64 acc[2][16];
    #pragma unroll
    for (int r = 0; r < 2; r++)
        #pragma unroll
        for (int c = 0; c < 16; c++) acc[r][c] = 0ull;

    for (int ic0 = 0; ic0 < 192; ic0 += ICB) {
        __syncthreads();
        for (int i = t; i < ICB * 9 * 64; i += 256) {
            int icl = i / 576, r = i - icl * 576;
            int tap = r >> 6, j = r & 63;
            s_w[i] = g_wt[((size_t)(wbase + ic0 + icl) * 9 + tap) * 192 + ocb + j];
        }
        for (int i = t; i < ICB * 1089; i += 256) {
            int icl = i & 3, pxi = i >> 2;
            int rr = pxi / 33, cc = pxi - rr * 33;
            float v = stage_val(inb, Hin, iy0 + rr, ix0 + cc, ic0 + icl,
                                bnin, mski, inrelu);
            s_in[icl * 1122 + rr * 34 + cc] = dup2(v);
        }
        __syncthreads();
        #pragma unroll
        for (int icl = 0; icl < ICB; icl++) {
            const u64* base = s_in + icl * 1122;
            const float* wp0 = s_w + icl * 576;
            #pragma unroll
            for (int dy = 0; dy < 3; dy++) {
                u64 w2[3];
                #pragma unroll
                for (int dx = 0; dx < 3; dx++)
                    w2[dx] = reinterpret_cast<const u64*>(wp0 + (dy * 3 + dx) * 64)[ln];
                #pragma unroll
                for (int r = 0; r < 2; r++) {
                    const u64* rp = base + (4 * wrp + 2 * r + dy) * 34;
                    #pragma unroll
                    for (int ch = 0; ch < 2; ch++) {
                        ulonglong2 W[9];
                        const ulonglong2* pW = reinterpret_cast<const ulonglong2*>(rp + ch * 16);
                        #pragma unroll
                        for (int k = 0; k < 9; k++) W[k] = pW[k];
                        #pragma unroll
                        for (int dx = 0; dx < 3; dx++)
                            #pragma unroll
                            for (int c = 0; c < 8; c++)
                                fma2(acc[r][ch * 8 + c], w2[dx], wsel(W, 2 * c + dx));
                    }
                }
            }
        }
    }

    const float* mo = maskptr(lvl) + (size_t)b * Hout * Hout;
    int oy0 = ty0 + 2 * wrp;
    u64 sum = 0ull, sq = 0ull;
    #pragma unroll
    for (int c = 0; c < 16; c++) {
        u64 m0 = dup2(mo[oy0 * Hout + tx0 + c]);
        u64 m1 = dup2(mo[(oy0 + 1) * Hout + tx0 + c]);
        fma2(sum, acc[0][c], m0); fma2(sq, mul2(acc[0][c], acc[0][c]), m0);
        fma2(sum, acc[1][c], m1); fma2(sq, mul2(acc[1][c], acc[1][c]), m1);
    }
    int oc = ocb + 2 * ln;
    float* ob = out + (size_t)b * Hout * Hout * 192 + oc;
    #pragma unroll
    for (int c = 0; c < 16; c++) {
        *(u64*)(ob + (size_t)(oy0 * Hout + tx0 + c) * 192) = acc[0][c];
        *(u64*)(ob + (size_t)((oy0 + 1) * Hout + tx0 + c) * 192) = acc[1][c];
    }
    stats_combine(s_red, t, ln, ocb, up2(sum), up2(sq));
}

// =============== 3x3 conv stride 1, 16x8 tile (small resolutions) ===============
__global__ void __launch_bounds__(256, 3)
k_conv_s1s(int srcb, int dstb, int wslot, int H, int inslot, int inrelu, int lvl) {
    constexpr int ICB = 8;
    __shared__ __align__(16) u64 s_in[ICB * 10 * 18];
    __shared__ __align__(16) float s_w[ICB * 9 * 64];
    __shared__ float s_red[128];

    const float* in = bufsel(srcb);
    float* out = bufsel(dstb);
    int tilesX = H >> 4;
    int tx0 = (blockIdx.x % tilesX) << 4;
    int ty0 = (blockIdx.x / tilesX) << 3;
    int b = blockIdx.y;
    int ocb = blockIdx.z * 64;
    int t = threadIdx.x, wrp = t >> 5, ln = t & 31;

    const float* inb = in + (size_t)b * H * H * 192;
    const float* mski = (inslot >= 0) ? maskptr(lvl) + (size_t)b * H * H : nullptr;
    const float* bnin = (inslot >= 0) ? g_bn2 + inslot * 384 : nullptr;
    const int wbase = wslot * 192;

    u64 acc[16];
    #pragma unroll
    for (int c = 0; c < 16; c++) acc[c] = 0ull;

    for (int ic0 = 0; ic0 < 192; ic0 += ICB) {
        __syncthreads();
        for (int i = t; i < ICB * 9 * 64; i += 256) {
            int icl = i / 576, r = i - icl * 576;
            int tap = r >> 6, j = r & 63;
            s_w[i] = g_wt[((size_t)(wbase + ic0 + icl) * 9 + tap) * 192 + ocb + j];
        }
        for (int i = t; i < ICB * 180; i += 256) {
            int icl = i & 7, pxi = i >> 3;
            int rr = pxi / 18, cc = pxi - rr * 18;
            float v = stage_val(inb, H, ty0 - 1 + rr, tx0 - 1 + cc, ic0 + icl,
                                bnin, mski, inrelu);
            s_in[icl * 180 + rr * 18 + cc] = dup2(v);
        }
        __syncthreads();
        #pragma unroll
        for (int icl = 0; icl < ICB; icl++) {
            const u64* base = s_in + icl * 180;
            const float* wp0 = s_w + icl * 576;
            #pragma unroll
            for (int dy = 0; dy < 3; dy++) {
                u64 w2[3];
                #pragma unroll
                for (int dx = 0; dx < 3; dx++)
                    w2[dx] = reinterpret_cast<const u64*>(wp0 + (dy * 3 + dx) * 64)[ln];
                const u64* rA = base + (wrp + dy) * 18;
                #pragma unroll
                for (int ch = 0; ch < 2; ch++) {
                    ulonglong2 W[5];
                    const ulonglong2* pA = reinterpret_cast<const ulonglong2*>(rA + ch * 8);
                    #pragma unroll
                    for (int k = 0; k < 5; k++) W[k] = pA[k];
                    #pragma unroll
                    for (int dx = 0; dx < 3; dx++)
                        #pragma unroll
                        for (int c = 0; c < 8; c++)
                            fma2(acc[ch * 8 + c], w2[dx], wsel(W, c + dx));
                }
            }
        }
    }

    const float* mo = maskptr(lvl) + (size_t)b * H * H;
    int oy = ty0 + wrp;
    u64 sum = 0ull, sq = 0ull;
    #pragma unroll
    for (int c = 0; c < 16; c++) {
        u64 md = dup2(mo[oy * H + tx0 + c]);
        fma2(sum, acc[c], md);
        fma2(sq, mul2(acc[c], acc[c]), md);
    }
    int oc = ocb + 2 * ln;
    float* ob = out + (size_t)b * H * H * 192 + oc;
    #pragma unroll
    for (int c = 0; c < 16; c++)
        *(u64*)(ob + (size_t)(oy * H + tx0 + c) * 192) = acc[c];
    stats_combine(s_red, t, ln, ocb, up2(sum), up2(sq));
}

// ---------------- BN finalize ----------------
__global__ void k_finalize(int slot, const float* __restrict__ g,
                           const float* __restrict__ bt, int lvl) {
    int c = threadIdx.x;
    float cnt = fmaxf(g_cnt[lvl], 1.f);
    float mean = g_stats[c] / cnt;
    float var = fmaxf(g_stats[HD + c] / cnt - mean * mean, 0.f);
    float inv = rsqrtf(var + BN_EPS);
    float sc = g[c] * inv;
    g_bn2[slot * 384 + c] = sc;
    g_bn2[slot * 384 + HD + c] = bt[c] - mean * sc;
}

// final apply: NHWC -> NCHW external out, BN + mask + relu
__global__ void k_apply1(int srcb, int slot, float* __restrict__ dst) {
    const float* x = bufsel(srcb);
    const float* bn = g_bn2 + slot * 384;
    int i = blockIdx.x * 256 + threadIdx.x;   // NB*192*256
    if (i >= NB * 192 * 256) return;
    int p = i & 255;
    int c = (i >> 8) % 192;
    int b = i / (192 * 256);
    float v = (x[((size_t)(b * 256 + p)) * 192 + c] * bn[c] + bn[192 + c]) * g_m4[b * 256 + p];
    dst[i] = fmaxf(v, 0.f);
}

// residual combine (NHWC): relu( bn_a(x)*m + bn_b(idn)*m ) -> dst
__global__ void k_apply2(int srcb, int sa, int idnb, int sb, int dstb, int lvl, int HW) {
    const float* x = bufsel(srcb);
    const float* idn = bufsel(idnb);
    float* dst = bufsel(dstb);
    const float* m = maskptr(lvl);
    const float* bna = g_bn2 + sa * 384;
    const float* bnb = g_bn2 + sb * 384;
    int total = NB * HW * 192;
    for (int i = blockIdx.x * 256 + threadIdx.x; i < total; i += gridDim.x * 256) {
        int c = i % 192;
        int r = i / 192;
        int p = r % HW, b = r / HW;
        float mm = m[b * HW + p];
        float v = (x[i] * bna[c] + bna[192 + c]) * mm;
        float w = (idn[i] * bnb[c] + bnb[192 + c]) * mm;
        dst[i] = fmaxf(v + w, 0.f);
    }
}

// final 1x1 conv 192->192 at res 16 (NHWC A -> NHWC B), fused masked stats
__global__ void k_fin(const float* __restrict__ w) {
    __shared__ float sx[192];
    int bp = blockIdx.x;                 // b*256 + p
    int t = threadIdx.x;
    sx[t] = g_A[(size_t)bp * 192 + t];
    __syncthreads();
    const float* wr = w + t * 192;
    float s = 0.f;
    #pragma unroll 8
    for (int ic = 0; ic < 192; ic++) s += __ldg(wr + ic) * sx[ic];
    g_Bu[(size_t)bp * 192 + t] = s;
    float m = g_m4[bp];
    atomicAdd(&g_stats[t], s * m);
    atomicAdd(&g_stats[HD + t], s * s * m);
}

__global__ void k_aux(const int* __restrict__ mask, float* __restrict__ out) {
    int i = blockIdx.x * 256 + threadIdx.x;
    if (i < 2048) {
        out[393216 + i] = (float)mask[i];
        out[395264 + i] = (float)(i & 255);
    }
}

// ---------------- host orchestration ----------------
extern "C" void kernel_launch(void* const* d_in, const int* in_sizes, int n_in,
                              void* d_out, int out_size) {
    const float* images = (const float*)d_in[0];
    const int* mask = (const int*)d_in[1];
    const float* stem_w = (const float*)d_in[2];
    const float* stem_g = (const float*)d_in[3];
    const float* stem_b = (const float*)d_in[4];
    const float* dw1 = (const float*)d_in[5];
    const float* dg1 = (const float*)d_in[6];
    const float* db1 = (const float*)d_in[7];
    const float* dw2 = (const float*)d_in[8];
    const float* dg2 = (const float*)d_in[9];
    const float* db2 = (const float*)d_in[10];
    const float* rw1 = (const float*)d_in[11];
    const float* rg1 = (const float*)d_in[12];
    const float* rb1 = (const float*)d_in[13];
    const float* rw2 = (const float*)d_in[14];
    const float* rg2 = (const float*)d_in[15];
    const float* rb2 = (const float*)d_in[16];
    const float* fw = (const float*)d_in[17];
    const float* fg = (const float*)d_in[18];
    const float* fb = (const float*)d_in[19];
    float* out = (float*)d_out;

    k_zcnt<<<1, 32>>>();
    k_mask0<<<NB * 65536 / 256, 256>>>(mask);
    k_down<<<NB * 128 * 128 / 256, 256>>>(1, 256, 128);
    k_down<<<NB * 64 * 64 / 256, 256>>>(2, 128, 64);
    k_down<<<NB * 32 * 32 / 256, 256>>>(3, 64, 32);
    k_down<<<NB * 16 * 16 / 256, 256>>>(4, 32, 16);
    k_wt<<<8192, 256>>>(dw1, dw2, rw1, rw2);

    // stem: raw NHWC conv + analytic BN stats (slot 0)
    k_stem<<<NB * 65536 * 96 / 256, 256>>>(images, stem_w);
    k_mom<<<512, 256>>>(images);
    k_finstem<<<1, 192>>>(stem_w, stem_g, stem_b);

    int Hin = 256;
    for (int i = 0; i < 4; i++) {
        int Hout = Hin / 2;
        int HW = Hout * Hout;
        int lvl = i + 1;
        int tiles = Hout / 16;
        dim3 g16(tiles * tiles, NB, 3);
        dim3 g8(tiles * (Hout / 8), NB, 3);
        bool small = (Hout <= 32);

        // d1 (stride 2): A -> B raw, stats -> slot 4i+1
        k_zstat<<<1, 2 * HD>>>();
        k_conv_s2<<<g16, 256>>>(0, 1, 4 * i + 0, Hout,
                                (i == 0 ? 0 : -1), (i == 0 ? 1 : 0), lvl);
        k_finalize<<<1, 192>>>(4 * i + 1, dg1 + i * 192, db1 + i * 192, lvl);

        // d2: B -> C raw (input slot d1, relu), stats -> slot 4i+2
        k_zstat<<<1, 2 * HD>>>();
        if (small) k_conv_s1s<<<g8, 256>>>(1, 2, 4 * i + 1, Hout, 4 * i + 1, 1, lvl);
        else       k_conv_s1<<<g16, 256>>>(1, 2, 4 * i + 1, Hout, 4 * i + 1, 1, lvl);
        k_finalize<<<1, 192>>>(4 * i + 2, dg2 + i * 192, db2 + i * 192, lvl);

        // r1: C -> B raw (input slot d2, NO relu), stats -> slot 4i+3
        k_zstat<<<1, 2 * HD>>>();
        if (small) k_conv_s1s<<<g8, 256>>>(2, 1, 4 * i + 2, Hout, 4 * i + 2, 0, lvl);
        else       k_conv_s1<<<g16, 256>>>(2, 1, 4 * i + 2, Hout, 4 * i + 2, 0, lvl);
        k_finalize<<<1, 192>>>(4 * i + 3, rg1 + i * 192, rb1 + i * 192, lvl);

        // r2: B -> A raw (input slot r1, relu), stats -> slot 4i+4
        k_zstat<<<1, 2 * HD>>>();
        if (small) k_conv_s1s<<<g8, 256>>>(1, 0, 4 * i + 3, Hout, 4 * i + 3, 1, lvl);
        else       k_conv_s1<<<g16, 256>>>(1, 0, 4 * i + 3, Hout, 4 * i + 3, 1, lvl);
        k_finalize<<<1, 192>>>(4 * i + 4, rg2 + i * 192, rb2 + i * 192, lvl);

        // residual combine: relu(bn_{r2}(A)*m + bn_{d2}(C)*m) -> A
        int blocks = std::min(8192, (NB * HW * 192 + 255) / 256);
        k_apply2<<<blocks, 256>>>(0, 4 * i + 4, 2, 4 * i + 2, 0, lvl, HW);
        Hin = Hout;
    }

    // final 1x1 proj: A@16 -> B raw (fused stats), finalize slot 17, apply -> out
    k_zstat<<<1, 2 * HD>>>();
    k_fin<<<NB * 256, 192>>>(fw);
    k_finalize<<<1, 192>>>(17, fg, fb, 4);
    k_apply1<<<NB * 192 * 256 / 256, 256>>>(1, 17, out);

    if (out_size >= 397312) k_aux<<<8, 256>>>(mask, out);
}

// round 13
// speedup vs baseline: 1.1083x; 1.1083x over previous
#include <cuda_runtime.h>
#include <algorithm>

static constexpr int NB = 8;
static constexpr int HD = 192;
#define BN_EPS 1e-5f

typedef unsigned long long u64;

// ---------------- scratch (static device memory; no allocations) ----------------
// Activation buffers are NHWC: [b][y][x][c]
__device__ float g_A[(size_t)NB * HD * 256 * 256];
__device__ float g_Bu[(size_t)NB * HD * 128 * 128];
__device__ float g_Cu[(size_t)NB * HD * 128 * 128];
__device__ float g_m0[NB * 256 * 256];
__device__ float g_m1[NB * 128 * 128];
__device__ float g_m2[NB * 64 * 64];
__device__ float g_m3[NB * 32 * 32];
__device__ float g_m4[NB * 16 * 16];
__device__ float g_wt[16 * 192 * 9 * 192];           // [conv][ic][tap][oc]
__device__ float g_stats[2 * HD];
__device__ float g_cnt[5];
__device__ float g_mom[9];                           // masked image moments (stem BN)
__device__ float g_bn2[18 * 2 * HD];

__device__ __forceinline__ float* bufsel(int i) {
    return (i == 0) ? g_A : (i == 1) ? g_Bu : g_Cu;
}
__device__ __forceinline__ float* maskptr(int lvl) {
    switch (lvl) {
        case 0: return g_m0;
        case 1: return g_m1;
        case 2: return g_m2;
        case 3: return g_m3;
        default: return g_m4;
    }
}

// ---------------- packed fp32x2 helpers ----------------
__device__ __forceinline__ void fma2(u64& d, u64 a, u64 b) {
    asm("fma.rn.f32x2 %0, %1, %2, %0;" : "+l"(d) : "l"(a), "l"(b));
}
__device__ __forceinline__ u64 mul2(u64 a, u64 b) {
    u64 d; asm("mul.rn.f32x2 %0, %1, %2;" : "=l"(d) : "l"(a), "l"(b)); return d;
}
__device__ __forceinline__ u64 dup2(float x) {
    unsigned int u = __float_as_uint(x);
    return (u64)u | ((u64)u << 32);
}
__device__ __forceinline__ u64 pack2(float x, float y) {
    u64 d; asm("mov.b64 %0, {%1, %2};" : "=l"(d) : "f"(x), "f"(y)); return d;
}
__device__ __forceinline__ float2 up2(u64 v) {
    float2 f;
    f.x = __uint_as_float((unsigned int)v);
    f.y = __uint_as_float((unsigned int)(v >> 32));
    return f;
}
__device__ __forceinline__ u64 wsel(const ulonglong2* W, int j) {
    return (j & 1) ? W[j >> 1].y : W[j >> 1].x;
}

// ---------------- small utility kernels ----------------
__global__ void k_zcnt() {
    if (threadIdx.x < 5) g_cnt[threadIdx.x] = 0.f;
    if (threadIdx.x < 9) g_mom[threadIdx.x] = 0.f;
}
__global__ void k_zstat() { if (threadIdx.x < 2 * HD) g_stats[threadIdx.x] = 0.f; }

__global__ void k_mask0(const int* __restrict__ mask) {
    int i = blockIdx.x * 256 + threadIdx.x;
    int b = i >> 16, p = i & 65535;
    int y = p >> 8, x = p & 255;
    float v = 1.f - (float)mask[b * 256 + (y >> 4) * 16 + (x >> 4)];
    g_m0[i] = v;
    float s = v;
    for (int o = 16; o; o >>= 1) s += __shfl_down_sync(0xffffffffu, s, o);
    if ((threadIdx.x & 31) == 0) atomicAdd(&g_cnt[0], s);
}

__global__ void k_down(int lvl, int Hin, int Hout) {
    const float* mi = maskptr(lvl - 1);
    float* mo = maskptr(lvl);
    int HW = Hout * Hout;
    int i = blockIdx.x * 256 + threadIdx.x;
    int b = i / HW, p = i - b * HW;
    int y = p / Hout, x = p - y * Hout;
    float mx = 0.f;
    #pragma unroll
    for (int dy = 0; dy < 3; dy++) {
        int yy = 2 * y - 1 + dy;
        if (yy < 0 || yy >= Hin) continue;
        #pragma unroll
        for (int dx = 0; dx < 3; dx++) {
            int xx = 2 * x - 1 + dx;
            if (xx < 0 || xx >= Hin) continue;
            mx = fmaxf(mx, mi[(b * Hin + yy) * Hin + xx]);
        }
    }
    mo[i] = mx;
    float s = mx;
    for (int o = 16; o; o >>= 1) s += __shfl_down_sync(0xffffffffu, s, o);
    if ((threadIdx.x & 31) == 0) atomicAdd(&g_cnt[lvl], s);
}

__global__ void k_wt(const float* __restrict__ dw1, const float* __restrict__ dw2,
                     const float* __restrict__ rw1, const float* __restrict__ rw2) {
    const size_t per = 192 * 9 * 192;
    const size_t total = 16 * per;
    for (size_t i = (size_t)blockIdx.x * blockDim.x + threadIdx.x; i < total;
         i += (size_t)gridDim.x * blockDim.x) {
        int conv = (int)(i / per);
        int r = (int)(i - (size_t)conv * per);
        int ic = r / (9 * 192);
        int r2 = r - ic * (9 * 192);
        int tap = r2 / 192, oc = r2 - tap * 192;
        int layer = conv >> 2, kind = conv & 3;
        const float* src = (kind == 0 ? dw1 : kind == 1 ? dw2 : kind == 2 ? rw1 : rw2)
                           + (size_t)layer * per;
        g_wt[i] = src[(size_t)oc * 1728 + ic * 9 + tap];
    }
}

// stem: 1x1 conv 3->192, NHWC raw output (stats handled analytically)
__global__ void k_stem(const float* __restrict__ img, const float* __restrict__ w) {
    size_t i = (size_t)blockIdx.x * 256 + threadIdx.x;  // NB*65536*96
    int op = (int)(i % 96);
    size_t r = i / 96;
    int p = (int)(r & 65535);
    int b = (int)(r >> 16);
    const float* ib = img + (size_t)b * 196608 + p;
    float i0 = ib[0], i1 = ib[65536], i2 = ib[131072];
    int oc = op * 2;
    float v0 = w[oc * 3 + 0] * i0 + w[oc * 3 + 1] * i1 + w[oc * 3 + 2] * i2;
    float v1 = w[oc * 3 + 3] * i0 + w[oc * 3 + 4] * i1 + w[oc * 3 + 5] * i2;
    *(u64*)&g_A[((size_t)b * 65536 + p) * 192 + oc] = pack2(v0, v1);
}

// masked image moments: M1[3] + M2[6]
__global__ void k_mom(const float* __restrict__ img) {
    float a[9];
    #pragma unroll
    for (int j = 0; j < 9; j++) a[j] = 0.f;
    int N = NB * 65536;
    for (int i = blockIdx.x * 256 + threadIdx.x; i < N; i += gridDim.x * 256) {
        int b = i >> 16, p = i & 65535;
        const float* ib = img + (size_t)b * 196608 + p;
        float m = g_m0[i];
        float c0 = ib[0], c1 = ib[65536], c2 = ib[131072];
        a[0] += c0 * m; a[1] += c1 * m; a[2] += c2 * m;
        a[3] += c0 * c0 * m; a[4] += c0 * c1 * m; a[5] += c0 * c2 * m;
        a[6] += c1 * c1 * m; a[7] += c1 * c2 * m; a[8] += c2 * c2 * m;
    }
    #pragma unroll
    for (int j = 0; j < 9; j++)
        for (int o = 16; o; o >>= 1) a[j] += __shfl_down_sync(0xffffffffu, a[j], o);
    __shared__ float sh[8][9];
    int w = threadIdx.x >> 5, ln = threadIdx.x & 31;
    if (ln == 0) {
        #pragma unroll
        for (int j = 0; j < 9; j++) sh[w][j] = a[j];
    }
    __syncthreads();
    if (threadIdx.x < 9) {
        float s = 0.f;
        #pragma unroll
        for (int k = 0; k < 8; k++) s += sh[k][threadIdx.x];
        atomicAdd(&g_mom[threadIdx.x], s);
    }
}

// stem BN finalize from moments -> slot 0
__global__ void k_finstem(const float* __restrict__ w, const float* __restrict__ g,
                          const float* __restrict__ bt) {
    int c = threadIdx.x;
    float w0 = w[c * 3], w1 = w[c * 3 + 1], w2 = w[c * 3 + 2];
    float cnt = fmaxf(g_cnt[0], 1.f);
    float s = w0 * g_mom[0] + w1 * g_mom[1] + w2 * g_mom[2];
    float ss = w0 * w0 * g_mom[3] + w1 * w1 * g_mom[6] + w2 * w2 * g_mom[8]
             + 2.f * (w0 * w1 * g_mom[4] + w0 * w2 * g_mom[5] + w1 * w2 * g_mom[7]);
    float mean = s / cnt;
    float var = fmaxf(ss / cnt - mean * mean, 0.f);
    float inv = rsqrtf(var + BN_EPS);
    float sc = g[c] * inv;
    g_bn2[c] = sc;
    g_bn2[HD + c] = bt[c] - mean * sc;
}

// fused input transform during staging (NHWC read)
__device__ __forceinline__ float stage_val(const float* __restrict__ inb, int Hin,
                                           int yy, int xx, int c,
                                           const float* __restrict__ bnin,
                                           const float* __restrict__ mski, int inrelu) {
    if ((unsigned)yy >= (unsigned)Hin || (unsigned)xx >= (unsigned)Hin) return 0.f;
    float v = inb[((size_t)yy * Hin + xx) * 192 + c];
    if (bnin) {
        v = (v * bnin[c] + bnin[192 + c]) * mski[yy * Hin + xx];
        if (inrelu) v = fmaxf(v, 0.f);
    }
    return v;
}

// cross-warp stats combine: shared atomics then 128 global REDG
__device__ __forceinline__ void stats_combine(float* s_red, int t, int ln, int ocb,
                                              float2 sv, float2 qv) {
    __syncthreads();
    if (t < 128) s_red[t] = 0.f;
    __syncthreads();
    atomicAdd(&s_red[2 * ln], sv.x);
    atomicAdd(&s_red[2 * ln + 1], sv.y);
    atomicAdd(&s_red[64 + 2 * ln], qv.x);
    atomicAdd(&s_red[64 + 2 * ln + 1], qv.y);
    __syncthreads();
    if (t < 64) {
        atomicAdd(&g_stats[ocb + t], s_red[t]);
        atomicAdd(&g_stats[HD + ocb + t], s_red[64 + t]);
    }
}

// =============== 3x3 conv stride 1, 8x16 tile, 64 oc/block ===============
// 256 threads = 8 warps (2 output rows x 8 px each) x 32 lanes (oc-pair each)
// low register pressure: only one 5xLDS.128 row buffer live in the inner loop
__global__ void __launch_bounds__(256, 2)
k_conv_s1(int srcb, int dstb, int wslot, int H, int inslot, int inrelu, int lvl) {
    constexpr int ICB = 8;
    __shared__ __align__(16) u64 s_in[ICB * 18 * 10];
    __shared__ __align__(16) float s_w[ICB * 9 * 64];
    __shared__ float s_red[128];

    const float* in = bufsel(srcb);
    float* out = bufsel(dstb);
    int txs = H >> 3;
    int tx0 = (blockIdx.x % txs) << 3;
    int ty0 = (blockIdx.x / txs) << 4;
    int b = blockIdx.y;
    int ocb = blockIdx.z * 64;
    int t = threadIdx.x, wrp = t >> 5, ln = t & 31;

    const float* inb = in + (size_t)b * H * H * 192;
    const float* mski = (inslot >= 0) ? maskptr(lvl) + (size_t)b * H * H : nullptr;
    const float* bnin = (inslot >= 0) ? g_bn2 + inslot * 384 : nullptr;
    const int wbase = wslot * 192;

    u64 acc[2][8];
    #pragma unroll
    for (int r = 0; r < 2; r++)
        #pragma unroll
        for (int c = 0; c < 8; c++) acc[r][c] = 0ull;

    for (int ic0 = 0; ic0 < 192; ic0 += ICB) {
        __syncthreads();
        for (int i = t; i < ICB * 9 * 64; i += 256) {
            int icl = i / 576, r = i - icl * 576;
            int tap = r >> 6, j = r & 63;
            s_w[i] = g_wt[((size_t)(wbase + ic0 + icl) * 9 + tap) * 192 + ocb + j];
        }
        for (int i = t; i < ICB * 180; i += 256) {
            int icl = i & 7, pxi = i >> 3;
            int rr = pxi / 10, cc = pxi - rr * 10;
            float v = stage_val(inb, H, ty0 - 1 + rr, tx0 - 1 + cc, ic0 + icl,
                                bnin, mski, inrelu);
            s_in[icl * 180 + rr * 10 + cc] = dup2(v);
        }
        __syncthreads();
        #pragma unroll
        for (int icl = 0; icl < ICB; icl++) {
            const u64* base = s_in + icl * 180;
            const float* wp0 = s_w + icl * 576;
            #pragma unroll
            for (int dy = 0; dy < 3; dy++) {
                u64 w2[3];
                #pragma unroll
                for (int dx = 0; dx < 3; dx++)
                    w2[dx] = reinterpret_cast<const u64*>(wp0 + (dy * 3 + dx) * 64)[ln];
                #pragma unroll
                for (int r = 0; r < 2; r++) {
                    const ulonglong2* pR =
                        reinterpret_cast<const ulonglong2*>(base + (2 * wrp + r + dy) * 10);
                    ulonglong2 R[5];
                    #pragma unroll
                    for (int k = 0; k < 5; k++) R[k] = pR[k];
                    #pragma unroll
                    for (int dx = 0; dx < 3; dx++)
                        #pragma unroll
                        for (int c = 0; c < 8; c++)
                            fma2(acc[r][c], w2[dx], wsel(R, c + dx));
                }
            }
        }
    }

    const float* mo = maskptr(lvl) + (size_t)b * H * H;
    int oy0 = ty0 + 2 * wrp;
    u64 sum = 0ull, sq = 0ull;
    #pragma unroll
    for (int r = 0; r < 2; r++)
        #pragma unroll
        for (int c = 0; c < 8; c++) {
            u64 md = dup2(mo[(oy0 + r) * H + tx0 + c]);
            fma2(sum, acc[r][c], md);
            fma2(sq, mul2(acc[r][c], acc[r][c]), md);
        }
    int oc = ocb + 2 * ln;
    float* ob = out + (size_t)b * H * H * 192 + oc;
    #pragma unroll
    for (int r = 0; r < 2; r++)
        #pragma unroll
        for (int c = 0; c < 8; c++)
            *(u64*)(ob + (size_t)((oy0 + r) * H + tx0 + c) * 192) = acc[r][c];
    stats_combine(s_red, t, ln, ocb, up2(sum), up2(sq));
}

// =============== 3x3 conv stride 2, 8x16 output tile, 64 oc/block ===============
__global__ void __launch_bounds__(256, 2)
k_conv_s2(int srcb, int dstb, int wslot, int Hout, int inslot, int inrelu, int lvl) {
    constexpr int ICB = 4;
    __shared__ __align__(16) u64 s_in[ICB * 33 * 18];
    __shared__ __align__(16) float s_w[ICB * 9 * 64];
    __shared__ float s_red[128];

    const int Hin = Hout * 2;
    const float* in = bufsel(srcb);
    float* out = bufsel(dstb);
    int txs = Hout >> 3;
    int tx0 = (blockIdx.x % txs) << 3;
    int ty0 = (blockIdx.x / txs) << 4;
    int b = blockIdx.y;
    int ocb = blockIdx.z * 64;
    int t = threadIdx.x, wrp = t >> 5, ln = t & 31;

    const float* inb = in + (size_t)b * Hin * Hin * 192;
    const float* mski = (inslot >= 0) ? maskptr(lvl - 1) + (size_t)b * Hin * Hin : nullptr;
    const float* bnin = (inslot >= 0) ? g_bn2 + inslot * 384 : nullptr;
    const int wbase = wslot * 192;
    int iy0 = ty0 * 2 - 1, ix0 = tx0 * 2 - 1;

    u64 acc[2][8];
    #pragma unroll
    for (int r = 0; r < 2; r++)
        #pragma unroll
        for (int c = 0; c < 8; c++) acc[r][c] = 0ull;

    for (int ic0 = 0; ic0 < 192; ic0 += ICB) {
        __syncthreads();
        for (int i = t; i < ICB * 9 * 64; i += 256) {
            int icl = i / 576, r = i - icl * 576;
            int tap = r >> 6, j = r & 63;
            s_w[i] = g_wt[((size_t)(wbase + ic0 + icl) * 9 + tap) * 192 + ocb + j];
        }
        for (int i = t; i < ICB * 561; i += 256) {
            int icl = i & 3, pxi = i >> 2;
            int rr = pxi / 17, cc = pxi - rr * 17;
            float v = stage_val(inb, Hin, iy0 + rr, ix0 + cc, ic0 + icl,
                                bnin, mski, inrelu);
            s_in[icl * 594 + rr * 18 + cc] = dup2(v);
        }
        __syncthreads();
        #pragma unroll
        for (int icl = 0; icl < ICB; icl++) {
            const u64* base = s_in + icl * 594;
            const float* wp0 = s_w + icl * 576;
            #pragma unroll
            for (int dy = 0; dy < 3; dy++) {
                u64 w2[3];
                #pragma unroll
                for (int dx = 0; dx < 3; dx++)
                    w2[dx] = reinterpret_cast<const u64*>(wp0 + (dy * 3 + dx) * 64)[ln];
                #pragma unroll
                for (int r = 0; r < 2; r++) {
                    const u64* rp = base + (4 * wrp + 2 * r + dy) * 18;
                    #pragma unroll
                    for (int h = 0; h < 2; h++) {
                        const ulonglong2* pR =
                            reinterpret_cast<const ulonglong2*>(rp + h * 8);
                        ulonglong2 R[5];
                        #pragma unroll
                        for (int k = 0; k < 5; k++) R[k] = pR[k];
                        #pragma unroll
                        for (int dx = 0; dx < 3; dx++)
                            #pragma unroll
                            for (int c = 0; c < 4; c++)
                                fma2(acc[r][h * 4 + c], w2[dx], wsel(R, 2 * c + dx));
                    }
                }
            }
        }
    }

    const float* mo = maskptr(lvl) + (size_t)b * Hout * Hout;
    int oy0 = ty0 + 2 * wrp;
    u64 sum = 0ull, sq = 0ull;
    #pragma unroll
    for (int r = 0; r < 2; r++)
        #pragma unroll
        for (int c = 0; c < 8; c++) {
            u64 md = dup2(mo[(oy0 + r) * Hout + tx0 + c]);
            fma2(sum, acc[r][c], md);
            fma2(sq, mul2(acc[r][c], acc[r][c]), md);
        }
    int oc = ocb + 2 * ln;
    float* ob = out + (size_t)b * Hout * Hout * 192 + oc;
    #pragma unroll
    for (int r = 0; r < 2; r++)
        #pragma unroll
        for (int c = 0; c < 8; c++)
            *(u64*)(ob + (size_t)((oy0 + r) * Hout + tx0 + c) * 192) = acc[r][c];
    stats_combine(s_red, t, ln, ocb, up2(sum), up2(sq));
}

// =============== 3x3 conv stride 1, 8x8 tile (small resolutions) ===============
__global__ void __launch_bounds__(256, 2)
k_conv_s1s(int srcb, int dstb, int wslot, int H, int inslot, int inrelu, int lvl) {
    constexpr int ICB = 8;
    __shared__ __align__(16) u64 s_in[ICB * 10 * 10];
    __shared__ __align__(16) float s_w[ICB * 9 * 64];
    __shared__ float s_red[128];

    const float* in = bufsel(srcb);
    float* out = bufsel(dstb);
    int txs = H >> 3;
    int tx0 = (blockIdx.x % txs) << 3;
    int ty0 = (blockIdx.x / txs) << 3;
    int b = blockIdx.y;
    int ocb = blockIdx.z * 64;
    int t = threadIdx.x, wrp = t >> 5, ln = t & 31;

    const float* inb = in + (size_t)b * H * H * 192;
    const float* mski = (inslot >= 0) ? maskptr(lvl) + (size_t)b * H * H : nullptr;
    const float* bnin = (inslot >= 0) ? g_bn2 + inslot * 384 : nullptr;
    const int wbase = wslot * 192;

    u64 acc[8];
    #pragma unroll
    for (int c = 0; c < 8; c++) acc[c] = 0ull;

    for (int ic0 = 0; ic0 < 192; ic0 += ICB) {
        __syncthreads();
        for (int i = t; i < ICB * 9 * 64; i += 256) {
            int icl = i / 576, r = i - icl * 576;
            int tap = r >> 6, j = r & 63;
            s_w[i] = g_wt[((size_t)(wbase + ic0 + icl) * 9 + tap) * 192 + ocb + j];
        }
        for (int i = t; i < ICB * 100; i += 256) {
            int icl = i & 7, pxi = i >> 3;
            int rr = pxi / 10, cc = pxi - rr * 10;
            float v = stage_val(inb, H, ty0 - 1 + rr, tx0 - 1 + cc, ic0 + icl,
                                bnin, mski, inrelu);
            s_in[icl * 100 + rr * 10 + cc] = dup2(v);
        }
        __syncthreads();
        #pragma unroll
        for (int icl = 0; icl < ICB; icl++) {
            const u64* base = s_in + icl * 100;
            const float* wp0 = s_w + icl * 576;
            #pragma unroll
            for (int dy = 0; dy < 3; dy++) {
                u64 w2[3];
                #pragma unroll
                for (int dx = 0; dx < 3; dx++)
                    w2[dx] = reinterpret_cast<const u64*>(wp0 + (dy * 3 + dx) * 64)[ln];
                const ulonglong2* pR =
                    reinterpret_cast<const ulonglong2*>(base + (wrp + dy) * 10);
                ulonglong2 R[5];
                #pragma unroll
                for (int k = 0; k < 5; k++) R[k] = pR[k];
                #pragma unroll
                for (int dx = 0; dx < 3; dx++)
                    #pragma unroll
                    for (int c = 0; c < 8; c++)
                        fma2(acc[c], w2[dx], wsel(R, c + dx));
            }
        }
    }

    const float* mo = maskptr(lvl) + (size_t)b * H * H;
    int oy = ty0 + wrp;
    u64 sum = 0ull, sq = 0ull;
    #pragma unroll
    for (int c = 0; c < 8; c++) {
        u64 md = dup2(mo[oy * H + tx0 + c]);
        fma2(sum, acc[c], md);
        fma2(sq, mul2(acc[c], acc[c]), md);
    }
    int oc = ocb + 2 * ln;
    float* ob = out + (size_t)b * H * H * 192 + oc;
    #pragma unroll
    for (int c = 0; c < 8; c++)
        *(u64*)(ob + (size_t)(oy * H + tx0 + c) * 192) = acc[c];
    stats_combine(s_red, t, ln, ocb, up2(sum), up2(sq));
}

// ---------------- BN finalize ----------------
__global__ void k_finalize(int slot, const float* __restrict__ g,
                           const float* __restrict__ bt, int lvl) {
    int c = threadIdx.x;
    float cnt = fmaxf(g_cnt[lvl], 1.f);
    float mean = g_stats[c] / cnt;
    float var = fmaxf(g_stats[HD + c] / cnt - mean * mean, 0.f);
    float inv = rsqrtf(var + BN_EPS);
    float sc = g[c] * inv;
    g_bn2[slot * 384 + c] = sc;
    g_bn2[slot * 384 + HD + c] = bt[c] - mean * sc;
}

// final apply: NHWC -> NCHW external out, BN + mask + relu
__global__ void k_apply1(int srcb, int slot, float* __restrict__ dst) {
    const float* x = bufsel(srcb);
    const float* bn = g_bn2 + slot * 384;
    int i = blockIdx.x * 256 + threadIdx.x;   // NB*192*256
    if (i >= NB * 192 * 256) return;
    int p = i & 255;
    int c = (i >> 8) % 192;
    int b = i / (192 * 256);
    float v = (x[((size_t)(b * 256 + p)) * 192 + c] * bn[c] + bn[192 + c]) * g_m4[b * 256 + p];
    dst[i] = fmaxf(v, 0.f);
}

// residual combine (NHWC): relu( bn_a(x)*m + bn_b(idn)*m ) -> dst
__global__ void k_apply2(int srcb, int sa, int idnb, int sb, int dstb, int lvl, int HW) {
    const float* x = bufsel(srcb);
    const float* idn = bufsel(idnb);
    float* dst = bufsel(dstb);
    const float* m = maskptr(lvl);
    const float* bna = g_bn2 + sa * 384;
    const float* bnb = g_bn2 + sb * 384;
    int total = NB * HW * 192;
    for (int i = blockIdx.x * 256 + threadIdx.x; i < total; i += gridDim.x * 256) {
        int c = i % 192;
        int r = i / 192;
        int p = r % HW, b = r / HW;
        float mm = m[b * HW + p];
        float v = (x[i] * bna[c] + bna[192 + c]) * mm;
        float w = (idn[i] * bnb[c] + bnb[192 + c]) * mm;
        dst[i] = fmaxf(v + w, 0.f);
    }
}

// final 1x1 conv 192->192 at res 16 (NHWC A -> NHWC B), fused masked stats
__global__ void k_fin(const float* __restrict__ w) {
    __shared__ float sx[192];
    int bp = blockIdx.x;                 // b*256 + p
    int t = threadIdx.x;
    sx[t] = g_A[(size_t)bp * 192 + t];
    __syncthreads();
    const float* wr = w + t * 192;
    float s = 0.f;
    #pragma unroll 8
    for (int ic = 0; ic < 192; ic++) s += __ldg(wr + ic) * sx[ic];
    g_Bu[(size_t)bp * 192 + t] = s;
    float m = g_m4[bp];
    atomicAdd(&g_stats[t], s * m);
    atomicAdd(&g_stats[HD + t], s * s * m);
}

__global__ void k_aux(const int* __restrict__ mask, float* __restrict__ out) {
    int i = blockIdx.x * 256 + threadIdx.x;
    if (i < 2048) {
        out[393216 + i] = (float)mask[i];
        out[395264 + i] = (float)(i & 255);
    }
}

// ---------------- host orchestration ----------------
extern "C" void kernel_launch(void* const* d_in, const int* in_sizes, int n_in,
                              void* d_out, int out_size) {
    const float* images = (const float*)d_in[0];
    const int* mask = (const int*)d_in[1];
    const float* stem_w = (const float*)d_in[2];
    const float* stem_g = (const float*)d_in[3];
    const float* stem_b = (const float*)d_in[4];
    const float* dw1 = (const float*)d_in[5];
    const float* dg1 = (const float*)d_in[6];
    const float* db1 = (const float*)d_in[7];
    const float* dw2 = (const float*)d_in[8];
    const float* dg2 = (const float*)d_in[9];
    const float* db2 = (const float*)d_in[10];
    const float* rw1 = (const float*)d_in[11];
    const float* rg1 = (const float*)d_in[12];
    const float* rb1 = (const float*)d_in[13];
    const float* rw2 = (const float*)d_in[14];
    const float* rg2 = (const float*)d_in[15];
    const float* rb2 = (const float*)d_in[16];
    const float* fw = (const float*)d_in[17];
    const float* fg = (const float*)d_in[18];
    const float* fb = (const float*)d_in[19];
    float* out = (float*)d_out;

    k_zcnt<<<1, 32>>>();
    k_mask0<<<NB * 65536 / 256, 256>>>(mask);
    k_down<<<NB * 128 * 128 / 256, 256>>>(1, 256, 128);
    k_down<<<NB * 64 * 64 / 256, 256>>>(2, 128, 64);
    k_down<<<NB * 32 * 32 / 256, 256>>>(3, 64, 32);
    k_down<<<NB * 16 * 16 / 256, 256>>>(4, 32, 16);
    k_wt<<<8192, 256>>>(dw1, dw2, rw1, rw2);

    // stem: raw NHWC conv + analytic BN stats (slot 0)
    k_stem<<<NB * 65536 * 96 / 256, 256>>>(images, stem_w);
    k_mom<<<512, 256>>>(images);
    k_finstem<<<1, 192>>>(stem_w, stem_g, stem_b);

    int Hin = 256;
    for (int i = 0; i < 4; i++) {
        int Hout = Hin / 2;
        int HW = Hout * Hout;
        int lvl = i + 1;
        dim3 gmain((Hout / 8) * (Hout / 16), NB, 3);
        dim3 gsm((Hout / 8) * (Hout / 8), NB, 3);
        bool small = (Hout <= 32);

        // d1 (stride 2): A -> B raw, stats -> slot 4i+1
        k_zstat<<<1, 2 * HD>>>();
        k_conv_s2<<<gmain, 256>>>(0, 1, 4 * i + 0, Hout,
                                  (i == 0 ? 0 : -1), (i == 0 ? 1 : 0), lvl);
        k_finalize<<<1, 192>>>(4 * i + 1, dg1 + i * 192, db1 + i * 192, lvl);

        // d2: B -> C raw (input slot d1, relu), stats -> slot 4i+2
        k_zstat<<<1, 2 * HD>>>();
        if (small) k_conv_s1s<<<gsm, 256>>>(1, 2, 4 * i + 1, Hout, 4 * i + 1, 1, lvl);
        else       k_conv_s1<<<gmain, 256>>>(1, 2, 4 * i + 1, Hout, 4 * i + 1, 1, lvl);
        k_finalize<<<1, 192>>>(4 * i + 2, dg2 + i * 192, db2 + i * 192, lvl);

        // r1: C -> B raw (input slot d2, NO relu), stats -> slot 4i+3
        k_zstat<<<1, 2 * HD>>>();
        if (small) k_conv_s1s<<<gsm, 256>>>(2, 1, 4 * i + 2, Hout, 4 * i + 2, 0, lvl);
        else       k_conv_s1<<<gmain, 256>>>(2, 1, 4 * i + 2, Hout, 4 * i + 2, 0, lvl);
        k_finalize<<<1, 192>>>(4 * i + 3, rg1 + i * 192, rb1 + i * 192, lvl);

        // r2: B -> A raw (input slot r1, relu), stats -> slot 4i+4
        k_zstat<<<1, 2 * HD>>>();
        if (small) k_conv_s1s<<<gsm, 256>>>(1, 0, 4 * i + 3, Hout, 4 * i + 3, 1, lvl);
        else       k_conv_s1<<<gmain, 256>>>(1, 0, 4 * i + 3, Hout, 4 * i + 3, 1, lvl);
        k_finalize<<<1, 192>>>(4 * i + 4, rg2 + i * 192, rb2 + i * 192, lvl);

        // residual combine: relu(bn_{r2}(A)*m + bn_{d2}(C)*m) -> A
        int blocks = std::min(8192, (NB * HW * 192 + 255) / 256);
        k_apply2<<<blocks, 256>>>(0, 4 * i + 4, 2, 4 * i + 2, 0, lvl, HW);
        Hin = Hout;
    }

    // final 1x1 proj: A@16 -> B raw (fused stats), finalize slot 17, apply -> out
    k_zstat<<<1, 2 * HD>>>();
    k_fin<<<NB * 256, 192>>>(fw);
    k_finalize<<<1, 192>>>(17, fg, fb, 4);
    k_apply1<<<NB * 192 * 256 / 256, 256>>>(1, 17, out);

    if (out_size >= 397312) k_aux<<<8, 256>>>(mask, out);
}

// round 16
// speedup vs baseline: 1.1113x; 1.0027x over previous
#include <cuda_runtime.h>
#include <algorithm>

static constexpr int NB = 8;
static constexpr int HD = 192;
#define BN_EPS 1e-5f

typedef unsigned long long u64;

// ---------------- scratch (static device memory; no allocations) ----------------
// Activation buffers are NHWC: [b][y][x][c]
__device__ float g_A[(size_t)NB * HD * 256 * 256];
__device__ float g_Bu[(size_t)NB * HD * 128 * 128];
__device__ float g_Cu[(size_t)NB * HD * 128 * 128];
__device__ float g_m0[NB * 256 * 256];
__device__ float g_m1[NB * 128 * 128];
__device__ float g_m2[NB * 64 * 64];
__device__ float g_m3[NB * 32 * 32];
__device__ float g_m4[NB * 16 * 16];
__device__ float g_wt[16 * 192 * 9 * 192];           // [conv][ic][tap][oc]
__device__ float g_stats[2 * HD];
__device__ float g_cnt[5];
__device__ float g_mom[9];                           // masked image moments (stem BN)
__device__ float g_bn2[18 * 2 * HD];

__device__ __forceinline__ float* bufsel(int i) {
    return (i == 0) ? g_A : (i == 1) ? g_Bu : g_Cu;
}
__device__ __forceinline__ float* maskptr(int lvl) {
    switch (lvl) {
        case 0: return g_m0;
        case 1: return g_m1;
        case 2: return g_m2;
        case 3: return g_m3;
        default: return g_m4;
    }
}

// ---------------- packed fp32x2 helpers ----------------
__device__ __forceinline__ void fma2(u64& d, u64 a, u64 b) {
    asm("fma.rn.f32x2 %0, %1, %2, %0;" : "+l"(d) : "l"(a), "l"(b));
}
__device__ __forceinline__ u64 mul2(u64 a, u64 b) {
    u64 d; asm("mul.rn.f32x2 %0, %1, %2;" : "=l"(d) : "l"(a), "l"(b)); return d;
}
__device__ __forceinline__ u64 dup2(float x) {
    unsigned int u = __float_as_uint(x);
    return (u64)u | ((u64)u << 32);
}
__device__ __forceinline__ u64 pack2(float x, float y) {
    u64 d; asm("mov.b64 %0, {%1, %2};" : "=l"(d) : "f"(x), "f"(y)); return d;
}
__device__ __forceinline__ float2 up2(u64 v) {
    float2 f;
    f.x = __uint_as_float((unsigned int)v);
    f.y = __uint_as_float((unsigned int)(v >> 32));
    return f;
}
__device__ __forceinline__ u64 wsel(const ulonglong2* W, int j) {
    return (j & 1) ? W[j >> 1].y : W[j >> 1].x;
}

// ---------------- small utility kernels ----------------
__global__ void k_zcnt() {
    if (threadIdx.x < 5) g_cnt[threadIdx.x] = 0.f;
    if (threadIdx.x < 9) g_mom[threadIdx.x] = 0.f;
}
__global__ void k_zstat() { if (threadIdx.x < 2 * HD) g_stats[threadIdx.x] = 0.f; }

__global__ void k_mask0(const int* __restrict__ mask) {
    int i = blockIdx.x * 256 + threadIdx.x;
    int b = i >> 16, p = i & 65535;
    int y = p >> 8, x = p & 255;
    float v = 1.f - (float)mask[b * 256 + (y >> 4) * 16 + (x >> 4)];
    g_m0[i] = v;
    float s = v;
    for (int o = 16; o; o >>= 1) s += __shfl_down_sync(0xffffffffu, s, o);
    if ((threadIdx.x & 31) == 0) atomicAdd(&g_cnt[0], s);
}

__global__ void k_down(int lvl, int Hin, int Hout) {
    const float* mi = maskptr(lvl - 1);
    float* mo = maskptr(lvl);
    int HW = Hout * Hout;
    int i = blockIdx.x * 256 + threadIdx.x;
    int b = i / HW, p = i - b * HW;
    int y = p / Hout, x = p - y * Hout;
    float mx = 0.f;
    #pragma unroll
    for (int dy = 0; dy < 3; dy++) {
        int yy = 2 * y - 1 + dy;
        if (yy < 0 || yy >= Hin) continue;
        #pragma unroll
        for (int dx = 0; dx < 3; dx++) {
            int xx = 2 * x - 1 + dx;
            if (xx < 0 || xx >= Hin) continue;
            mx = fmaxf(mx, mi[(b * Hin + yy) * Hin + xx]);
        }
    }
    mo[i] = mx;
    float s = mx;
    for (int o = 16; o; o >>= 1) s += __shfl_down_sync(0xffffffffu, s, o);
    if ((threadIdx.x & 31) == 0) atomicAdd(&g_cnt[lvl], s);
}

__global__ void k_wt(const float* __restrict__ dw1, const float* __restrict__ dw2,
                     const float* __restrict__ rw1, const float* __restrict__ rw2) {
    const size_t per = 192 * 9 * 192;
    const size_t total = 16 * per;
    for (size_t i = (size_t)blockIdx.x * blockDim.x + threadIdx.x; i < total;
         i += (size_t)gridDim.x * blockDim.x) {
        int conv = (int)(i / per);
        int r = (int)(i - (size_t)conv * per);
        int ic = r / (9 * 192);
        int r2 = r - ic * (9 * 192);
        int tap = r2 / 192, oc = r2 - tap * 192;
        int layer = conv >> 2, kind = conv & 3;
        const float* src = (kind == 0 ? dw1 : kind == 1 ? dw2 : kind == 2 ? rw1 : rw2)
                           + (size_t)layer * per;
        g_wt[i] = src[(size_t)oc * 1728 + ic * 9 + tap];
    }
}

// stem: 1x1 conv 3->192, NHWC raw output (stats handled analytically)
__global__ void k_stem(const float* __restrict__ img, const float* __restrict__ w) {
    size_t i = (size_t)blockIdx.x * 256 + threadIdx.x;  // NB*65536*96
    int op = (int)(i % 96);
    size_t r = i / 96;
    int p = (int)(r & 65535);
    int b = (int)(r >> 16);
    const float* ib = img + (size_t)b * 196608 + p;
    float i0 = ib[0], i1 = ib[65536], i2 = ib[131072];
    int oc = op * 2;
    float v0 = w[oc * 3 + 0] * i0 + w[oc * 3 + 1] * i1 + w[oc * 3 + 2] * i2;
    float v1 = w[oc * 3 + 3] * i0 + w[oc * 3 + 4] * i1 + w[oc * 3 + 5] * i2;
    *(u64*)&g_A[((size_t)b * 65536 + p) * 192 + oc] = pack2(v0, v1);
}

// masked image moments: M1[3] + M2[6]
__global__ void k_mom(const float* __restrict__ img) {
    float a[9];
    #pragma unroll
    for (int j = 0; j < 9; j++) a[j] = 0.f;
    int N = NB * 65536;
    for (int i = blockIdx.x * 256 + threadIdx.x; i < N; i += gridDim.x * 256) {
        int b = i >> 16, p = i & 65535;
        const float* ib = img + (size_t)b * 196608 + p;
        float m = g_m0[i];
        float c0 = ib[0], c1 = ib[65536], c2 = ib[131072];
        a[0] += c0 * m; a[1] += c1 * m; a[2] += c2 * m;
        a[3] += c0 * c0 * m; a[4] += c0 * c1 * m; a[5] += c0 * c2 * m;
        a[6] += c1 * c1 * m; a[7] += c1 * c2 * m; a[8] += c2 * c2 * m;
    }
    #pragma unroll
    for (int j = 0; j < 9; j++)
        for (int o = 16; o; o >>= 1) a[j] += __shfl_down_sync(0xffffffffu, a[j], o);
    __shared__ float sh[8][9];
    int w = threadIdx.x >> 5, ln = threadIdx.x & 31;
    if (ln == 0) {
        #pragma unroll
        for (int j = 0; j < 9; j++) sh[w][j] = a[j];
    }
    __syncthreads();
    if (threadIdx.x < 9) {
        float s = 0.f;
        #pragma unroll
        for (int k = 0; k < 8; k++) s += sh[k][threadIdx.x];
        atomicAdd(&g_mom[threadIdx.x], s);
    }
}

// stem BN finalize from moments -> slot 0
__global__ void k_finstem(const float* __restrict__ w, const float* __restrict__ g,
                          const float* __restrict__ bt) {
    int c = threadIdx.x;
    float w0 = w[c * 3], w1 = w[c * 3 + 1], w2 = w[c * 3 + 2];
    float cnt = fmaxf(g_cnt[0], 1.f);
    float s = w0 * g_mom[0] + w1 * g_mom[1] + w2 * g_mom[2];
    float ss = w0 * w0 * g_mom[3] + w1 * w1 * g_mom[6] + w2 * w2 * g_mom[8]
             + 2.f * (w0 * w1 * g_mom[4] + w0 * w2 * g_mom[5] + w1 * w2 * g_mom[7]);
    float mean = s / cnt;
    float var = fmaxf(ss / cnt - mean * mean, 0.f);
    float inv = rsqrtf(var + BN_EPS);
    float sc = g[c] * inv;
    g_bn2[c] = sc;
    g_bn2[HD + c] = bt[c] - mean * sc;
}

// fused input transform during staging (NHWC read)
__device__ __forceinline__ float stage_val(const float* __restrict__ inb, int Hin,
                                           int yy, int xx, int c,
                                           const float* __restrict__ bnin,
                                           const float* __restrict__ mski, int inrelu) {
    if ((unsigned)yy >= (unsigned)Hin || (unsigned)xx >= (unsigned)Hin) return 0.f;
    float v = inb[((size_t)yy * Hin + xx) * 192 + c];
    if (bnin) {
        v = (v * bnin[c] + bnin[192 + c]) * mski[yy * Hin + xx];
        if (inrelu) v = fmaxf(v, 0.f);
    }
    return v;
}

// cross-warp stats combine: shared atomics then 128 global REDG
__device__ __forceinline__ void stats_combine(float* s_red, int t, int ln, int ocb,
                                              float2 sv, float2 qv) {
    __syncthreads();
    if (t < 128) s_red[t] = 0.f;
    __syncthreads();
    atomicAdd(&s_red[2 * ln], sv.x);
    atomicAdd(&s_red[2 * ln + 1], sv.y);
    atomicAdd(&s_red[64 + 2 * ln], qv.x);
    atomicAdd(&s_red[64 + 2 * ln + 1], qv.y);
    __syncthreads();
    if (t < 64) {
        atomicAdd(&g_stats[ocb + t], s_red[t]);
        atomicAdd(&g_stats[HD + ocb + t], s_red[64 + t]);
    }
}

// =============== 3x3 conv stride 1, 8x16 tile, 64 oc/block ===============
// 256 threads = 8 warps (2 output rows x 8 px each) x 32 lanes (oc-pair each)
// low register pressure: only one 5xLDS.128 row buffer live in the inner loop
__global__ void __launch_bounds__(256, 2)
k_conv_s1(int srcb, int dstb, int wslot, int H, int inslot, int inrelu, int lvl) {
    constexpr int ICB = 8;
    __shared__ __align__(16) u64 s_in[ICB * 18 * 10];
    __shared__ __align__(16) float s_w[ICB * 9 * 64];
    __shared__ float s_red[128];

    const float* in = bufsel(srcb);
    float* out = bufsel(dstb);
    int txs = H >> 3;
    int tx0 = (blockIdx.x % txs) << 3;
    int ty0 = (blockIdx.x / txs) << 4;
    int b = blockIdx.y;
    int ocb = blockIdx.z * 64;
    int t = threadIdx.x, wrp = t >> 5, ln = t & 31;

    const float* inb = in + (size_t)b * H * H * 192;
    const float* mski = (inslot >= 0) ? maskptr(lvl) + (size_t)b * H * H : nullptr;
    const float* bnin = (inslot >= 0) ? g_bn2 + inslot * 384 : nullptr;
    const int wbase = wslot * 192;

    u64 acc[2][8];
    #pragma unroll
    for (int r = 0; r < 2; r++)
        #pragma unroll
        for (int c = 0; c < 8; c++) acc[r][c] = 0ull;

    for (int ic0 = 0; ic0 < 192; ic0 += ICB) {
        __syncthreads();
        for (int i = t; i < ICB * 9 * 64; i += 256) {
            int icl = i / 576, r = i - icl * 576;
            int tap = r >> 6, j = r & 63;
            s_w[i] = g_wt[((size_t)(wbase + ic0 + icl) * 9 + tap) * 192 + ocb + j];
        }
        for (int i = t; i < ICB * 180; i += 256) {
            int icl = i & 7, pxi = i >> 3;
            int rr = pxi / 10, cc = pxi - rr * 10;
            float v = stage_val(inb, H, ty0 - 1 + rr, tx0 - 1 + cc, ic0 + icl,
                                bnin, mski, inrelu);
            s_in[icl * 180 + rr * 10 + cc] = dup2(v);
        }
        __syncthreads();
        #pragma unroll
        for (int icl = 0; icl < ICB; icl++) {
            const u64* base = s_in + icl * 180;
            const float* wp0 = s_w + icl * 576;
            #pragma unroll
            for (int dy = 0; dy < 3; dy++) {
                u64 w2[3];
                #pragma unroll
                for (int dx = 0; dx < 3; dx++)
                    w2[dx] = reinterpret_cast<const u64*>(wp0 + (dy * 3 + dx) * 64)[ln];
                #pragma unroll
                for (int r = 0; r < 2; r++) {
                    const ulonglong2* pR =
                        reinterpret_cast<const ulonglong2*>(base + (2 * wrp + r + dy) * 10);
                    ulonglong2 R[5];
                    #pragma unroll
                    for (int k = 0; k < 5; k++) R[k] = pR[k];
                    #pragma unroll
                    for (int dx = 0; dx < 3; dx++)
                        #pragma unroll
                        for (int c = 0; c < 8; c++)
                            fma2(acc[r][c], w2[dx], wsel(R, c + dx));
                }
            }
        }
    }

    const float* mo = maskptr(lvl) + (size_t)b * H * H;
    int oy0 = ty0 + 2 * wrp;
    u64 sum = 0ull, sq = 0ull;
    #pragma unroll
    for (int r = 0; r < 2; r++)
        #pragma unroll
        for (int c = 0; c < 8; c++) {
            u64 md = dup2(mo[(oy0 + r) * H + tx0 + c]);
            fma2(sum, acc[r][c], md);
            fma2(sq, mul2(acc[r][c], acc[r][c]), md);
        }
    int oc = ocb + 2 * ln;
    float* ob = out + (size_t)b * H * H * 192 + oc;
    #pragma unroll
    for (int r = 0; r < 2; r++)
        #pragma unroll
        for (int c = 0; c < 8; c++)
            *(u64*)(ob + (size_t)((oy0 + r) * H + tx0 + c) * 192) = acc[r][c];
    stats_combine(s_red, t, ln, ocb, up2(sum), up2(sq));
}

// =============== 3x3 conv stride 2, 8x16 output tile, 64 oc/block ===============
__global__ void __launch_bounds__(256, 2)
k_conv_s2(int srcb, int dstb, int wslot, int Hout, int inslot, int inrelu, int lvl) {
    constexpr int ICB = 4;
    __shared__ __align__(16) u64 s_in[ICB * 33 * 18];
    __shared__ __align__(16) float s_w[ICB * 9 * 64];
    __shared__ float s_red[128];

    const int Hin = Hout * 2;
    const float* in = bufsel(srcb);
    float* out = bufsel(dstb);
    int txs = Hout >> 3;
    int tx0 = (blockIdx.x % txs) << 3;
    int ty0 = (blockIdx.x / txs) << 4;
    int b = blockIdx.y;
    int ocb = blockIdx.z * 64;
    int t = threadIdx.x, wrp = t >> 5, ln = t & 31;

    const float* inb = in + (size_t)b * Hin * Hin * 192;
    const float* mski = (inslot >= 0) ? maskptr(lvl - 1) + (size_t)b * Hin * Hin : nullptr;
    const float* bnin = (inslot >= 0) ? g_bn2 + inslot * 384 : nullptr;
    const int wbase = wslot * 192;
    int iy0 = ty0 * 2 - 1, ix0 = tx0 * 2 - 1;

    u64 acc[2][8];
    #pragma unroll
    for (int r = 0; r < 2; r++)
        #pragma unroll
        for (int c = 0; c < 8; c++) acc[r][c] = 0ull;

    for (int ic0 = 0; ic0 < 192; ic0 += ICB) {
        __syncthreads();
        for (int i = t; i < ICB * 9 * 64; i += 256) {
            int icl = i / 576, r = i - icl * 576;
            int tap = r >> 6, j = r & 63;
            s_w[i] = g_wt[((size_t)(wbase + ic0 + icl) * 9 + tap) * 192 + ocb + j];
        }
        for (int i = t; i < ICB * 561; i += 256) {
            int icl = i & 3, pxi = i >> 2;
            int rr = pxi / 17, cc = pxi - rr * 17;
            float v = stage_val(inb, Hin, iy0 + rr, ix0 + cc, ic0 + icl,
                                bnin, mski, inrelu);
            s_in[icl * 594 + rr * 18 + cc] = dup2(v);
        }
        __syncthreads();
        #pragma unroll
        for (int icl = 0; icl < ICB; icl++) {
            const u64* base = s_in + icl * 594;
            const float* wp0 = s_w + icl * 576;
            #pragma unroll
            for (int dy = 0; dy < 3; dy++) {
                u64 w2[3];
                #pragma unroll
                for (int dx = 0; dx < 3; dx++)
                    w2[dx] = reinterpret_cast<const u64*>(wp0 + (dy * 3 + dx) * 64)[ln];
                #pragma unroll
                for (int r = 0; r < 2; r++) {
                    const u64* rp = base + (4 * wrp + 2 * r + dy) * 18;
                    #pragma unroll
                    for (int h = 0; h < 2; h++) {
                        const ulonglong2* pR =
                            reinterpret_cast<const ulonglong2*>(rp + h * 8);
                        ulonglong2 R[5];
                        #pragma unroll
                        for (int k = 0; k < 5; k++) R[k] = pR[k];
                        #pragma unroll
                        for (int dx = 0; dx < 3; dx++)
                            #pragma unroll
                            for (int c = 0; c < 4; c++)
                                fma2(acc[r][h * 4 + c], w2[dx], wsel(R, 2 * c + dx));
                    }
                }
            }
        }
    }

    const float* mo = maskptr(lvl) + (size_t)b * Hout * Hout;
    int oy0 = ty0 + 2 * wrp;
    u64 sum = 0ull, sq = 0ull;
    #pragma unroll
    for (int r = 0; r < 2; r++)
        #pragma unroll
        for (int c = 0; c < 8; c++) {
            u64 md = dup2(mo[(oy0 + r) * Hout + tx0 + c]);
            fma2(sum, acc[r][c], md);
            fma2(sq, mul2(acc[r][c], acc[r][c]), md);
        }
    int oc = ocb + 2 * ln;
    float* ob = out + (size_t)b * Hout * Hout * 192 + oc;
    #pragma unroll
    for (int r = 0; r < 2; r++)
        #pragma unroll
        for (int c = 0; c < 8; c++)
            *(u64*)(ob + (size_t)((oy0 + r) * Hout + tx0 + c) * 192) = acc[r][c];
    stats_combine(s_red, t, ln, ocb, up2(sum), up2(sq));
}

// =============== 3x3 conv stride 1, 8x8 tile (small resolutions) ===============
__global__ void __launch_bounds__(256, 2)
k_conv_s1s(int srcb, int dstb, int wslot, int H, int inslot, int inrelu, int lvl) {
    constexpr int ICB = 8;
    __shared__ __align__(16) u64 s_in[ICB * 10 * 10];
    __shared__ __align__(16) float s_w[ICB * 9 * 64];
    __shared__ float s_red[128];

    const float* in = bufsel(srcb);
    float* out = bufsel(dstb);
    int txs = H >> 3;
    int tx0 = (blockIdx.x % txs) << 3;
    int ty0 = (blockIdx.x / txs) << 3;
    int b = blockIdx.y;
    int ocb = blockIdx.z * 64;
    int t = threadIdx.x, wrp = t >> 5, ln = t & 31;

    const float* inb = in + (size_t)b * H * H * 192;
    const float* mski = (inslot >= 0) ? maskptr(lvl) + (size_t)b * H * H : nullptr;
    const float* bnin = (inslot >= 0) ? g_bn2 + inslot * 384 : nullptr;
    const int wbase = wslot * 192;

    u64 acc[8];
    #pragma unroll
    for (int c = 0; c < 8; c++) acc[c] = 0ull;

    for (int ic0 = 0; ic0 < 192; ic0 += ICB) {
        __syncthreads();
        for (int i = t; i < ICB * 9 * 64; i += 256) {
            int icl = i / 576, r = i - icl * 576;
            int tap = r >> 6, j = r & 63;
            s_w[i] = g_wt[((size_t)(wbase + ic0 + icl) * 9 + tap) * 192 + ocb + j];
        }
        for (int i = t; i < ICB * 100; i += 256) {
            int icl = i & 7, pxi = i >> 3;
            int rr = pxi / 10, cc = pxi - rr * 10;
            float v = stage_val(inb, H, ty0 - 1 + rr, tx0 - 1 + cc, ic0 + icl,
                                bnin, mski, inrelu);
            s_in[icl * 100 + rr * 10 + cc] = dup2(v);
        }
        __syncthreads();
        #pragma unroll
        for (int icl = 0; icl < ICB; icl++) {
            const u64* base = s_in + icl * 100;
            const float* wp0 = s_w + icl * 576;
            #pragma unroll
            for (int dy = 0; dy < 3; dy++) {
                u64 w2[3];
                #pragma unroll
                for (int dx = 0; dx < 3; dx++)
                    w2[dx] = reinterpret_cast<const u64*>(wp0 + (dy * 3 + dx) * 64)[ln];
                const ulonglong2* pR =
                    reinterpret_cast<const ulonglong2*>(base + (wrp + dy) * 10);
                ulonglong2 R[5];
                #pragma unroll
                for (int k = 0; k < 5; k++) R[k] = pR[k];
                #pragma unroll
                for (int dx = 0; dx < 3; dx++)
                    #pragma unroll
                    for (int c = 0; c < 8; c++)
                        fma2(acc[c], w2[dx], wsel(R, c + dx));
            }
        }
    }

    const float* mo = maskptr(lvl) + (size_t)b * H * H;
    int oy = ty0 + wrp;
    u64 sum = 0ull, sq = 0ull;
    #pragma unroll
    for (int c = 0; c < 8; c++) {
        u64 md = dup2(mo[oy * H + tx0 + c]);
        fma2(sum, acc[c], md);
        fma2(sq, mul2(acc[c], acc[c]), md);
    }
    int oc = ocb + 2 * ln;
    float* ob = out + (size_t)b * H * H * 192 + oc;
    #pragma unroll
    for (int c = 0; c < 8; c++)
        *(u64*)(ob + (size_t)(oy * H + tx0 + c) * 192) = acc[c];
    stats_combine(s_red, t, ln, ocb, up2(sum), up2(sq));
}

// ---------------- BN finalize ----------------
__global__ void k_finalize(int slot, const float* __restrict__ g,
                           const float* __restrict__ bt, int lvl) {
    int c = threadIdx.x;
    float cnt = fmaxf(g_cnt[lvl], 1.f);
    float mean = g_stats[c] / cnt;
    float var = fmaxf(g_stats[HD + c] / cnt - mean * mean, 0.f);
    float inv = rsqrtf(var + BN_EPS);
    float sc = g[c] * inv;
    g_bn2[slot * 384 + c] = sc;
    g_bn2[slot * 384 + HD + c] = bt[c] - mean * sc;
}

// final apply: NHWC -> NCHW external out, BN + mask + relu
__global__ void k_apply1(int srcb, int slot, float* __restrict__ dst) {
    const float* x = bufsel(srcb);
    const float* bn = g_bn2 + slot * 384;
    int i = blockIdx.x * 256 + threadIdx.x;   // NB*192*256
    if (i >= NB * 192 * 256) return;
    int p = i & 255;
    int c = (i >> 8) % 192;
    int b = i / (192 * 256);
    float v = (x[((size_t)(b * 256 + p)) * 192 + c] * bn[c] + bn[192 + c]) * g_m4[b * 256 + p];
    dst[i] = fmaxf(v, 0.f);
}

// residual combine (NHWC): relu( bn_a(x)*m + bn_b(idn)*m ) -> dst
__global__ void k_apply2(int srcb, int sa, int idnb, int sb, int dstb, int lvl, int HW) {
    const float* x = bufsel(srcb);
    const float* idn = bufsel(idnb);
    float* dst = bufsel(dstb);
    const float* m = maskptr(lvl);
    const float* bna = g_bn2 + sa * 384;
    const float* bnb = g_bn2 + sb * 384;
    int total = NB * HW * 192;
    for (int i = blockIdx.x * 256 + threadIdx.x; i < total; i += gridDim.x * 256) {
        int c = i % 192;
        int r = i / 192;
        int p = r % HW, b = r / HW;
        float mm = m[b * HW + p];
        float v = (x[i] * bna[c] + bna[192 + c]) * mm;
        float w = (idn[i] * bnb[c] + bnb[192 + c]) * mm;
        dst[i] = fmaxf(v + w, 0.f);
    }
}

// final 1x1 conv 192->192 at res 16 (NHWC A -> NHWC B), fused masked stats
__global__ void k_fin(const float* __restrict__ w) {
    __shared__ float sx[192];
    int bp = blockIdx.x;                 // b*256 + p
    int t = threadIdx.x;
    sx[t] = g_A[(size_t)bp * 192 + t];
    __syncthreads();
    const float* wr = w + t * 192;
    float s = 0.f;
    #pragma unroll 8
    for (int ic = 0; ic < 192; ic++) s += __ldg(wr + ic) * sx[ic];
    g_Bu[(size_t)bp * 192 + t] = s;
    float m = g_m4[bp];
    atomicAdd(&g_stats[t], s * m);
    atomicAdd(&g_stats[HD + t], s * s * m);
}

__global__ void k_aux(const int* __restrict__ mask, float* __restrict__ out) {
    int i = blockIdx.x * 256 + threadIdx.x;
    if (i < 2048) {
        out[393216 + i] = (float)mask[i];
        out[395264 + i] = (float)(i & 255);
    }
}

// ---------------- host orchestration ----------------
extern "C" void kernel_launch(void* const* d_in, const int* in_sizes, int n_in,
                              void* d_out, int out_size) {
    const float* images = (const float*)d_in[0];
    const int* mask = (const int*)d_in[1];
    const float* stem_w = (const float*)d_in[2];
    const float* stem_g = (const float*)d_in[3];
    const float* stem_b = (const float*)d_in[4];
    const float* dw1 = (const float*)d_in[5];
    const float* dg1 = (const float*)d_in[6];
    const float* db1 = (const float*)d_in[7];
    const float* dw2 = (const float*)d_in[8];
    const float* dg2 = (const float*)d_in[9];
    const float* db2 = (const float*)d_in[10];
    const float* rw1 = (const float*)d_in[11];
    const float* rg1 = (const float*)d_in[12];
    const float* rb1 = (const float*)d_in[13];
    const float* rw2 = (const float*)d_in[14];
    const float* rg2 = (const float*)d_in[15];
    const float* rb2 = (const float*)d_in[16];
    const float* fw = (const float*)d_in[17];
    const float* fg = (const float*)d_in[18];
    const float* fb = (const float*)d_in[19];
    float* out = (float*)d_out;

    k_zcnt<<<1, 32>>>();
    k_mask0<<<NB * 65536 / 256, 256>>>(mask);
    k_down<<<NB * 128 * 128 / 256, 256>>>(1, 256, 128);
    k_down<<<NB * 64 * 64 / 256, 256>>>(2, 128, 64);
    k_down<<<NB * 32 * 32 / 256, 256>>>(3, 64, 32);
    k_down<<<NB * 16 * 16 / 256, 256>>>(4, 32, 16);
    k_wt<<<8192, 256>>>(dw1, dw2, rw1, rw2);

    // stem: raw NHWC conv + analytic BN stats (slot 0)
    k_stem<<<NB * 65536 * 96 / 256, 256>>>(images, stem_w);
    k_mom<<<512, 256>>>(images);
    k_finstem<<<1, 192>>>(stem_w, stem_g, stem_b);

    int Hin = 256;
    for (int i = 0; i < 4; i++) {
        int Hout = Hin / 2;
        int HW = Hout * Hout;
        int lvl = i + 1;
        dim3 gmain((Hout / 8) * (Hout / 16), NB, 3);
        dim3 gsm((Hout / 8) * (Hout / 8), NB, 3);
        bool small = (Hout <= 32);

        // d1 (stride 2): A -> B raw, stats -> slot 4i+1
        k_zstat<<<1, 2 * HD>>>();
        k_conv_s2<<<gmain, 256>>>(0, 1, 4 * i + 0, Hout,
                                  (i == 0 ? 0 : -1), (i == 0 ? 1 : 0), lvl);
        k_finalize<<<1, 192>>>(4 * i + 1, dg1 + i * 192, db1 + i * 192, lvl);

        // d2: B -> C raw (input slot d1, relu), stats -> slot 4i+2
        k_zstat<<<1, 2 * HD>>>();
        if (small) k_conv_s1s<<<gsm, 256>>>(1, 2, 4 * i + 1, Hout, 4 * i + 1, 1, lvl);
        else       k_conv_s1<<<gmain, 256>>>(1, 2, 4 * i + 1, Hout, 4 * i + 1, 1, lvl);
        k_finalize<<<1, 192>>>(4 * i + 2, dg2 + i * 192, db2 + i * 192, lvl);

        // r1: C -> B raw (input slot d2, NO relu), stats -> slot 4i+3
        k_zstat<<<1, 2 * HD>>>();
        if (small) k_conv_s1s<<<gsm, 256>>>(2, 1, 4 * i + 2, Hout, 4 * i + 2, 0, lvl);
        else       k_conv_s1<<<gmain, 256>>>(2, 1, 4 * i + 2, Hout, 4 * i + 2, 0, lvl);
        k_finalize<<<1, 192>>>(4 * i + 3, rg1 + i * 192, rb1 + i * 192, lvl);

        // r2: B -> A raw (input slot r1, relu), stats -> slot 4i+4
        k_zstat<<<1, 2 * HD>>>();
        if (small) k_conv_s1s<<<gsm, 256>>>(1, 0, 4 * i + 3, Hout, 4 * i + 3, 1, lvl);
        else       k_conv_s1<<<gmain, 256>>>(1, 0, 4 * i + 3, Hout, 4 * i + 3, 1, lvl);
        k_finalize<<<1, 192>>>(4 * i + 4, rg2 + i * 192, rb2 + i * 192, lvl);

        // residual combine: relu(bn_{r2}(A)*m + bn_{d2}(C)*m) -> A
        int blocks = std::min(8192, (NB * HW * 192 + 255) / 256);
        k_apply2<<<blocks, 256>>>(0, 4 * i + 4, 2, 4 * i + 2, 0, lvl, HW);
        Hin = Hout;
    }

    // final 1x1 proj: A@16 -> B raw (fused stats), finalize slot 17, apply -> out
    k_zstat<<<1, 2 * HD>>>();
    k_fin<<<NB * 256, 192>>>(fw);
    k_finalize<<<1, 192>>>(17, fg, fb, 4);
    k_apply1<<<NB * 192 * 256 / 256, 256>>>(1, 17, out);

    if (out_size >= 397312) k_aux<<<8, 256>>>(mask, out);
}